// round 2
// baseline (speedup 1.0000x reference)
#include <cuda_runtime.h>

#define NN 4096
#define TI 8            // rows (i) per CTA: one per warp
#define THREADS 256
#define JITER (NN / 64) // 64 j's per warp-iteration (2 per lane)

// ---- packed fp32x2 helpers (sm_103a) ----
__device__ __forceinline__ unsigned long long pack2(float a, float b) {
    unsigned long long r;
    asm("mov.b64 %0, {%1, %2};" : "=l"(r) : "f"(a), "f"(b));
    return r;
}
__device__ __forceinline__ unsigned long long fma2(unsigned long long a,
                                                   unsigned long long b,
                                                   unsigned long long c) {
    unsigned long long d;
    asm("fma.rn.f32x2 %0, %1, %2, %3;" : "=l"(d) : "l"(a), "l"(b), "l"(c));
    return d;
}
__device__ __forceinline__ float2 unpack2(unsigned long long v) {
    float lo, hi;
    asm("mov.b64 {%0, %1}, %2;" : "=f"(lo), "=f"(hi) : "l"(v));
    return make_float2(lo, hi);
}

__global__ void __launch_bounds__(THREADS) ode_main(
    const float* __restrict__ x,   const float* __restrict__ A,
    const float* __restrict__ WA0, const float* __restrict__ bA0,
    const float* __restrict__ WA1, const float* __restrict__ bA1,
    const float* __restrict__ WA2, const float* __restrict__ bA2,
    const float* __restrict__ Wm0, const float* __restrict__ bm0,
    const float* __restrict__ Wm1, const float* __restrict__ bm1,
    const float* __restrict__ wA,  const float* __restrict__ wf,
    float* __restrict__ out)
{
    __shared__ float xs[NN];                       // full x vector (16 KB)
    __shared__ unsigned long long W1p[16][8];      // [k][l2] = (W1[2l2][k], W1[2l2+1][k])
    __shared__ float wvs[16];                      // WA0[k][1]
    __shared__ float W2s[16];

    const int tid = threadIdx.x;

    for (int idx = tid; idx < NN; idx += THREADS) xs[idx] = x[idx];
    if (tid < 128) {
        int k = tid >> 3, l2 = tid & 7;
        W1p[k][l2] = pack2(WA1[(2 * l2) * 16 + k], WA1[(2 * l2 + 1) * 16 + k]);
    }
    if (tid < 16) { wvs[tid] = WA0[2 * tid + 1]; W2s[tid] = WA2[tid]; }
    __syncthreads();

    const int warp = tid >> 5;
    const int lane = tid & 31;
    const int i = blockIdx.x * TI + warp;
    const float xi = xs[i];

    // per-i layer-0 offsets: u[k] = WA0[k][0]*x_i + bA0[k]
    float u[16];
    #pragma unroll
    for (int k = 0; k < 16; k++)
        u[k] = fmaf(WA0[2 * k], xi, bA0[k]);

    // layer-1 bias pairs held in registers
    unsigned long long bias[8];
    #pragma unroll
    for (int l2 = 0; l2 < 8; l2++)
        bias[l2] = pack2(bA1[2 * l2], bA1[2 * l2 + 1]);

    // ci = bA2 + wA[0]*x_i  (per-edge constant part of x_e + x_12)
    const float ci   = fmaf(wA[0], xi, bA2[0]);
    const float wA1c = wA[1];

    const float* __restrict__ Arow = A + (size_t)i * NN;
    float xA = 0.0f;

    for (int it = 0; it < JITER; it++) {
        const int j = (it << 6) + (lane << 1);
        const float2 xj  = *reinterpret_cast<const float2*>(xs + j);
        const float2 Aij = *reinterpret_cast<const float2*>(Arow + j);

        unsigned long long acc0[8], acc1[8];
        #pragma unroll
        for (int l2 = 0; l2 < 8; l2++) { acc0[l2] = bias[l2]; acc1[l2] = bias[l2]; }

        #pragma unroll
        for (int k = 0; k < 16; k++) {
            const float wvk = wvs[k];
            const float h0a = fmaxf(fmaf(wvk, xj.x, u[k]), 0.0f);
            const float h0b = fmaxf(fmaf(wvk, xj.y, u[k]), 0.0f);
            const unsigned long long ha = pack2(h0a, h0a);
            const unsigned long long hb = pack2(h0b, h0b);

            // W1 column k: 8 packed pairs, loaded as 4x LDS.128 (broadcast)
            const ulonglong2* wp = reinterpret_cast<const ulonglong2*>(W1p[k]);
            #pragma unroll
            for (int q = 0; q < 4; q++) {
                const ulonglong2 w = wp[q];
                acc0[2 * q]     = fma2(w.x, ha, acc0[2 * q]);
                acc1[2 * q]     = fma2(w.x, hb, acc1[2 * q]);
                acc0[2 * q + 1] = fma2(w.y, ha, acc0[2 * q + 1]);
                acc1[2 * q + 1] = fma2(w.y, hb, acc1[2 * q + 1]);
            }
        }

        // epilogue: relu(h1) . W2 + ci, then + wA[1]*x_j, weighted by A
        float s0 = ci, s1 = ci;
        #pragma unroll
        for (int l2 = 0; l2 < 8; l2++) {
            const float2 w2 = reinterpret_cast<const float2*>(W2s)[l2];
            const float2 a0 = unpack2(acc0[l2]);
            const float2 a1 = unpack2(acc1[l2]);
            s0 = fmaf(w2.x, fmaxf(a0.x, 0.0f), s0);
            s0 = fmaf(w2.y, fmaxf(a0.y, 0.0f), s0);
            s1 = fmaf(w2.x, fmaxf(a1.x, 0.0f), s1);
            s1 = fmaf(w2.y, fmaxf(a1.y, 0.0f), s1);
        }
        const float r0 = fmaf(wA1c, xj.x, s0);
        const float r1 = fmaf(wA1c, xj.y, s1);
        xA = fmaf(Aij.x, r0, xA);
        xA = fmaf(Aij.y, r1, xA);
    }

    // warp reduction over lanes (each warp owns exactly one i)
    #pragma unroll
    for (int off = 16; off; off >>= 1)
        xA += __shfl_down_sync(0xffffffffu, xA, off);

    if (lane == 0) {
        // node MLP branch: relu(x*Wm0 + bm0) . Wm1 + bm1 + wf*x
        float xn = fmaf(wf[0], xi, bm1[0]);
        #pragma unroll
        for (int k = 0; k < 16; k++)
            xn = fmaf(Wm1[k], fmaxf(fmaf(Wm0[k], xi, bm0[k]), 0.0f), xn);
        out[i] = xn + xA;
    }
}

extern "C" void kernel_launch(void* const* d_in, const int* in_sizes, int n_in,
                              void* d_out, int out_size) {
    // input order: t, x, A, WA0, bA0, WA1, bA1, WA2, bA2, Wm0, bm0, Wm1, bm1, wA, wf
    const float* x   = (const float*)d_in[1];
    const float* A   = (const float*)d_in[2];
    const float* WA0 = (const float*)d_in[3];
    const float* bA0 = (const float*)d_in[4];
    const float* WA1 = (const float*)d_in[5];
    const float* bA1 = (const float*)d_in[6];
    const float* WA2 = (const float*)d_in[7];
    const float* bA2 = (const float*)d_in[8];
    const float* Wm0 = (const float*)d_in[9];
    const float* bm0 = (const float*)d_in[10];
    const float* Wm1 = (const float*)d_in[11];
    const float* bm1 = (const float*)d_in[12];
    const float* wA  = (const float*)d_in[13];
    const float* wf  = (const float*)d_in[14];
    float* out = (float*)d_out;

    ode_main<<<NN / TI, THREADS>>>(x, A, WA0, bA0, WA1, bA1, WA2, bA2,
                                   Wm0, bm0, Wm1, bm1, wA, wf, out);
}

// round 3
// speedup vs baseline: 3.9218x; 3.9218x over previous
#include <cuda_runtime.h>
#include <math.h>

#define NN 4096
#define MAXSEG 512

// scratch: piecewise-linear tables per row i (static device memory — no allocs)
__device__ float g_B[NN * MAXSEG];   // segment left boundaries (B[0] = -1e38)
__device__ float g_c[NN * MAXSEG];   // f(x) = c + d*x per segment
__device__ float g_d[NN * MAXSEG];
__device__ int   g_cnt[NN];

__device__ __forceinline__ float warp_sum(float v) {
    #pragma unroll
    for (int o = 16; o; o >>= 1) v += __shfl_xor_sync(0xffffffffu, v, o);
    return v;
}
__device__ __forceinline__ float warp_min(float v) {
    #pragma unroll
    for (int o = 16; o; o >>= 1) v = fminf(v, __shfl_xor_sync(0xffffffffu, v, o));
    return v;
}

// ---------------- build kernel: one warp per row i ----------------
__global__ void __launch_bounds__(256) build_pwl(
    const float* __restrict__ x,
    const float* __restrict__ WA0, const float* __restrict__ bA0,
    const float* __restrict__ WA1, const float* __restrict__ bA1,
    const float* __restrict__ WA2, const float* __restrict__ bA2,
    const float* __restrict__ wA)
{
    __shared__ float sT[8][16];
    const int warp = threadIdx.x >> 5, lane = threadIdx.x & 31;
    const int i = blockIdx.x * 8 + warp;
    const float xi = x[i];

    // lane k (<16): layer-0 affine pieces u_k + v_k * x_j
    float u = 0.f, v = 0.f, w2 = 0.f, b1l = 0.f;
    float w1[16];
    #pragma unroll
    for (int k = 0; k < 16; k++) w1[k] = 0.f;
    if (lane < 16) {
        u  = fmaf(WA0[2 * lane], xi, bA0[lane]);
        v  = WA0[2 * lane + 1];
        w2 = WA2[lane];
        b1l = bA1[lane];
        #pragma unroll
        for (int k = 0; k < 16; k++) w1[k] = WA1[lane * 16 + k];
    }

    // layer-0 knots, sorted by rank
    const bool tv = (lane < 16) && (fabsf(v) > 1e-30f);
    const float tk = tv ? (-u / v) : 3e30f;
    int rank = 0;
    #pragma unroll
    for (int k = 0; k < 16; k++) {
        float o = __shfl_sync(0xffffffffu, tk, k);
        rank += (o < tk) || (o == tk && k < lane);
    }
    const int nk = __popc(__ballot_sync(0xffffffffu, tv) & 0xffffu);
    if (lane < 16) sT[warp][rank] = tk;
    __syncwarp();

    const float cbase = fmaf(wA[0], xi, bA2[0]);
    const float dbase = wA[1];

    int cnt = 0;
    for (int s0 = 0; s0 <= nk; s0++) {
        const float lo = (s0 == 0)  ? -1e30f : sT[warp][s0 - 1];
        const float hi = (s0 == nk) ?  1e30f : sT[warp][s0];
        if (!(hi > lo)) continue;                    // warp-uniform
        const float mid = 0.5f * lo + 0.5f * hi;

        // h1_l = al + be * x  on this interval (lane l owns l)
        float al = b1l, be = 0.f;
        #pragma unroll
        for (int k = 0; k < 16; k++) {
            const float uk = __shfl_sync(0xffffffffu, u, k);
            const float vk = __shfl_sync(0xffffffffu, v, k);
            if (fmaf(vk, mid, uk) > 0.f) {          // layer-0 activity on interval
                al = fmaf(w1[k], uk, al);
                be = fmaf(w1[k], vk, be);
            }
        }
        if (lane >= 16) { al = 0.f; be = 0.f; }

        // interior zero-crossings of h1_l
        const float z = -al / be;
        bool zv = (lane < 16) && (fabsf(be) > 1e-30f) && (z > lo) && (z < hi);

        float cur = lo;
        while (true) {
            const float zc = zv ? z : 3e30f;
            const float b  = fminf(warp_min(zc), hi);   // next boundary (uniform)
            const float m2 = 0.5f * cur + 0.5f * b;
            const bool sgn = (lane < 16) && (fmaf(be, m2, al) > 0.f);
            float cc = sgn ? w2 * al : 0.f;
            float dd = sgn ? w2 * be : 0.f;
            cc = warp_sum(cc); dd = warp_sum(dd);
            if (lane == 0) {
                g_B[i * MAXSEG + cnt] = (cnt == 0) ? -1e38f : cur;
                g_c[i * MAXSEG + cnt] = cbase + cc;
                g_d[i * MAXSEG + cnt] = dbase + dd;
            }
            cnt++;
            if (!(b < hi)) break;
            if (zv && z <= b) zv = false;
            cur = b;
        }
    }

    // pad boundaries to pow2 for branchless search
    int P = 1; while (P < cnt) P <<= 1;
    for (int s = cnt + lane; s < P; s += 32) g_B[i * MAXSEG + s] = 3e38f;
    if (lane == 0) g_cnt[i] = cnt;
}

// ---------------- main pass: one CTA per row i ----------------
__global__ void __launch_bounds__(256) pwl_apply(
    const float* __restrict__ x, const float* __restrict__ A,
    const float* __restrict__ Wm0, const float* __restrict__ bm0,
    const float* __restrict__ Wm1, const float* __restrict__ bm1,
    const float* __restrict__ wf,
    float* __restrict__ out)
{
    __shared__ float sB[MAXSEG], sc[MAXSEG], sd[MAXSEG];
    __shared__ float red[256];
    const int i = blockIdx.x, tid = threadIdx.x;
    const int cnt = g_cnt[i];
    int P = 1; while (P < cnt) P <<= 1;

    for (int s = tid; s < P; s += 256) {
        sB[s] = g_B[i * MAXSEG + s];
        sc[s] = g_c[i * MAXSEG + s];
        sd[s] = g_d[i * MAXSEG + s];
    }
    __syncthreads();

    const float* __restrict__ Arow = A + (size_t)i * NN;
    float acc = 0.f;
    #pragma unroll
    for (int jj = 0; jj < NN / (256 * 4); jj++) {
        const int j = (jj * 256 + tid) * 4;
        const float4 a4 = *reinterpret_cast<const float4*>(Arow + j);
        const float4 x4 = *reinterpret_cast<const float4*>(x + j);
        const float xs4[4] = {x4.x, x4.y, x4.z, x4.w};
        const float as4[4] = {a4.x, a4.y, a4.z, a4.w};
        #pragma unroll
        for (int e = 0; e < 4; e++) {
            const float xj = xs4[e];
            int pos = 0;
            for (int st = P >> 1; st; st >>= 1)
                if (sB[pos + st] <= xj) pos += st;
            acc = fmaf(as4[e], fmaf(sd[pos], xj, sc[pos]), acc);
        }
    }

    red[tid] = acc;
    __syncthreads();
    #pragma unroll
    for (int s = 128; s; s >>= 1) {
        if (tid < s) red[tid] += red[tid + s];
        __syncthreads();
    }
    if (tid == 0) {
        const float xi = x[i];
        float xn = fmaf(wf[0], xi, bm1[0]);
        #pragma unroll
        for (int k = 0; k < 16; k++)
            xn = fmaf(Wm1[k], fmaxf(fmaf(Wm0[k], xi, bm0[k]), 0.f), xn);
        out[i] = xn + red[0];
    }
}

extern "C" void kernel_launch(void* const* d_in, const int* in_sizes, int n_in,
                              void* d_out, int out_size) {
    // input order: t, x, A, WA0, bA0, WA1, bA1, WA2, bA2, Wm0, bm0, Wm1, bm1, wA, wf
    const float* x   = (const float*)d_in[1];
    const float* A   = (const float*)d_in[2];
    const float* WA0 = (const float*)d_in[3];
    const float* bA0 = (const float*)d_in[4];
    const float* WA1 = (const float*)d_in[5];
    const float* bA1 = (const float*)d_in[6];
    const float* WA2 = (const float*)d_in[7];
    const float* bA2 = (const float*)d_in[8];
    const float* Wm0 = (const float*)d_in[9];
    const float* bm0 = (const float*)d_in[10];
    const float* Wm1 = (const float*)d_in[11];
    const float* bm1 = (const float*)d_in[12];
    const float* wA  = (const float*)d_in[13];
    const float* wf  = (const float*)d_in[14];
    float* out = (float*)d_out;

    build_pwl<<<NN / 8, 256>>>(x, WA0, bA0, WA1, bA1, WA2, bA2, wA);
    pwl_apply<<<NN, 256>>>(x, A, Wm0, bm0, Wm1, bm1, wf, out);
}

// round 4
// speedup vs baseline: 5.0818x; 1.2958x over previous
#include <cuda_runtime.h>
#include <math.h>

#define NN 4096
#define MAXSEG 512
#define GCELLS 1024
#define FULLM 0xffffffffu

// scratch: piecewise-linear tables per row i (static device memory — no allocs)
__device__ float g_B[NN * MAXSEG];   // segment left boundaries (B[0] = -1e38)
__device__ float g_c[NN * MAXSEG];   // f(x) = c + d*x per segment
__device__ float g_d[NN * MAXSEG];
__device__ int   g_cnt[NN];

__device__ __forceinline__ float warp_sum(float v) {
    #pragma unroll
    for (int o = 16; o; o >>= 1) v += __shfl_xor_sync(FULLM, v, o);
    return v;
}
__device__ __forceinline__ float warp_min(float v) {
    #pragma unroll
    for (int o = 16; o; o >>= 1) v = fminf(v, __shfl_xor_sync(FULLM, v, o));
    return v;
}

// ---------------- build kernel: one warp per row i ----------------
__global__ void __launch_bounds__(256) build_pwl(
    const float* __restrict__ x,
    const float* __restrict__ WA0, const float* __restrict__ bA0,
    const float* __restrict__ WA1, const float* __restrict__ bA1,
    const float* __restrict__ WA2, const float* __restrict__ bA2,
    const float* __restrict__ wA)
{
    __shared__ float sW1T[256];          // [k][l] = WA1[l][k] (row-independent)
    __shared__ float sT[8][16];
    __shared__ int   sK[8][16];
    const int warp = threadIdx.x >> 5, lane = threadIdx.x & 31;

    {
        int idx = threadIdx.x;           // 256 threads, 256 entries
        int k = idx >> 4, l = idx & 15;
        sW1T[idx] = WA1[l * 16 + k];
    }
    __syncthreads();

    const int i = blockIdx.x * 8 + warp;
    const float xi = x[i];

    // lane k (<16): layer-0 affine pieces u_k + v_k * x_j
    float u = 0.f, v = 0.f, w2 = 0.f, b1l = 0.f;
    if (lane < 16) {
        u   = fmaf(WA0[2 * lane], xi, bA0[lane]);
        v   = WA0[2 * lane + 1];
        w2  = WA2[lane];
        b1l = bA1[lane];
    }

    // layer-0 knots, rank-sorted; store knot value + owner k
    const bool tv = (lane < 16) && (fabsf(v) > 1e-30f);
    const float tk = tv ? (-u / v) : 3e30f;
    int rank = 0;
    #pragma unroll
    for (int k = 0; k < 16; k++) {
        float o = __shfl_sync(FULLM, tk, k);
        rank += (o < tk) || (o == tk && k < lane);
    }
    const int nk = __popc(__ballot_sync(FULLM, tv) & 0xffffu);
    if (tv) { sT[warp][rank] = tk; sK[warp][rank] = lane; }
    __syncwarp();

    // initial active set at x -> -inf
    const unsigned actmask =
        __ballot_sync(FULLM, (lane < 16) && ((v < 0.f) || (v == 0.f && u > 0.f)));

    // initial h1_l = al + be*x (lane l owns l)
    float al = b1l, be = 0.f;
    #pragma unroll
    for (int k = 0; k < 16; k++) {
        const float uk = __shfl_sync(FULLM, u, k);
        const float vk = __shfl_sync(FULLM, v, k);
        if (actmask & (1u << k)) {
            const float w1lk = sW1T[k * 16 + (lane & 15)];
            al = fmaf(w1lk, uk, al);
            be = fmaf(w1lk, vk, be);
        }
    }
    if (lane >= 16) { al = 0.f; be = 0.f; }

    const float cbase = fmaf(wA[0], xi, bA2[0]);
    const float dbase = wA[1];

    int cnt = 0;
    for (int s0 = 0; s0 <= nk; s0++) {
        // incremental flip of the knot we just crossed (also for degenerate intervals)
        if (s0 > 0) {
            const int kst = sK[warp][s0 - 1];
            const float uk = __shfl_sync(FULLM, u, kst);
            const float vk = __shfl_sync(FULLM, v, kst);
            if (lane < 16) {
                const float w1lk = sW1T[kst * 16 + lane];
                const float sw = (vk > 0.f) ? w1lk : -w1lk;  // v>0: activates; v<0: deactivates
                al = fmaf(sw, uk, al);
                be = fmaf(sw, vk, be);
            }
        }
        const float lo = (s0 == 0)  ? -1e30f : sT[warp][s0 - 1];
        const float hi = (s0 == nk) ?  1e30f : sT[warp][s0];
        if (!(hi > lo)) continue;                 // warp-uniform

        // interior zero-crossings of h1_l
        const float z = -al / be;
        bool zv = (lane < 16) && (fabsf(be) > 1e-30f) && (z > lo) && (z < hi);

        float cur = lo;
        while (true) {
            const float zc = zv ? z : 3e30f;
            const float b  = fminf(warp_min(zc), hi);   // next boundary (uniform)
            const float m2 = 0.5f * cur + 0.5f * b;
            const bool sgn = (lane < 16) && (fmaf(be, m2, al) > 0.f);
            float cc = sgn ? w2 * al : 0.f;
            float dd = sgn ? w2 * be : 0.f;
            cc = warp_sum(cc); dd = warp_sum(dd);
            if (lane == 0) {
                g_B[i * MAXSEG + cnt] = (cnt == 0) ? -1e38f : cur;
                g_c[i * MAXSEG + cnt] = cbase + cc;
                g_d[i * MAXSEG + cnt] = dbase + dd;
            }
            cnt++;
            if (!(b < hi)) break;
            if (zv && z <= b) zv = false;
            cur = b;
        }
    }

    // pad boundaries to pow2 for the LUT builder's branchless search
    int P = 1; while (P < cnt) P <<= 1;
    for (int s = cnt + lane; s < P; s += 32) g_B[i * MAXSEG + s] = 3e38f;
    if (lane == 0) g_cnt[i] = cnt;
}

// ---------------- main pass: one CTA per row i ----------------
__global__ void __launch_bounds__(256) pwl_apply(
    const float* __restrict__ x, const float* __restrict__ A,
    const float* __restrict__ Wm0, const float* __restrict__ bm0,
    const float* __restrict__ Wm1, const float* __restrict__ bm1,
    const float* __restrict__ wf,
    float* __restrict__ out)
{
    __shared__ float  sB[MAXSEG + 1];
    __shared__ float2 scd[MAXSEG];
    __shared__ unsigned short lut[GCELLS];
    __shared__ float red[256];
    const int i = blockIdx.x, tid = threadIdx.x;
    const int cnt = g_cnt[i];
    int P = 1; while (P < cnt) P <<= 1;

    for (int s = tid; s < P; s += 256) {
        sB[s]  = g_B[i * MAXSEG + s];
        scd[s] = make_float2(g_c[i * MAXSEG + s], g_d[i * MAXSEG + s]);
    }
    if (tid == 0) sB[P] = 3e38f;
    __syncthreads();

    // uniform-grid LUT over [-8, 8): lut[g] = seg(cell-g lower edge); cell 0 = -inf
    for (int g = tid; g < GCELLS; g += 256) {
        const float xg = (g == 0) ? -3e38f : fmaf((float)g, 1.0f / 64.0f, -8.0f);
        int pos = 0;
        for (int st = P >> 1; st; st >>= 1)
            if (sB[pos + st] <= xg) pos += st;
        lut[g] = (unsigned short)pos;
    }
    __syncthreads();

    const float* __restrict__ Arow = A + (size_t)i * NN;
    float acc = 0.f;
    #pragma unroll
    for (int jj = 0; jj < NN / (256 * 4); jj++) {
        const int j = (jj * 256 + tid) * 4;
        const float4 a4 = *reinterpret_cast<const float4*>(Arow + j);
        const float4 x4 = *reinterpret_cast<const float4*>(x + j);
        const float xa[4] = {x4.x, x4.y, x4.z, x4.w};
        const float aa[4] = {a4.x, a4.y, a4.z, a4.w};
        #pragma unroll
        for (int e = 0; e < 4; e++) {
            const float xj = xa[e];
            int idx = __float2int_rd(fmaf(xj, 64.f, 512.f));
            idx = min(max(idx, 0), GCELLS - 1);
            int s = (int)lut[idx];
            while (sB[s + 1] <= xj) s++;    // guard walk: almost never taken
            const float2 cd = scd[s];
            acc = fmaf(aa[e], fmaf(cd.y, xj, cd.x), acc);
        }
    }

    red[tid] = acc;
    __syncthreads();
    #pragma unroll
    for (int s = 128; s; s >>= 1) {
        if (tid < s) red[tid] += red[tid + s];
        __syncthreads();
    }
    if (tid == 0) {
        const float xi = x[i];
        float xn = fmaf(wf[0], xi, bm1[0]);
        #pragma unroll
        for (int k = 0; k < 16; k++)
            xn = fmaf(Wm1[k], fmaxf(fmaf(Wm0[k], xi, bm0[k]), 0.f), xn);
        out[i] = xn + red[0];
    }
}

extern "C" void kernel_launch(void* const* d_in, const int* in_sizes, int n_in,
                              void* d_out, int out_size) {
    // input order: t, x, A, WA0, bA0, WA1, bA1, WA2, bA2, Wm0, bm0, Wm1, bm1, wA, wf
    const float* x   = (const float*)d_in[1];
    const float* A   = (const float*)d_in[2];
    const float* WA0 = (const float*)d_in[3];
    const float* bA0 = (const float*)d_in[4];
    const float* WA1 = (const float*)d_in[5];
    const float* bA1 = (const float*)d_in[6];
    const float* WA2 = (const float*)d_in[7];
    const float* bA2 = (const float*)d_in[8];
    const float* Wm0 = (const float*)d_in[9];
    const float* bm0 = (const float*)d_in[10];
    const float* Wm1 = (const float*)d_in[11];
    const float* bm1 = (const float*)d_in[12];
    const float* wA  = (const float*)d_in[13];
    const float* wf  = (const float*)d_in[14];
    float* out = (float*)d_out;

    build_pwl<<<NN / 8, 256>>>(x, WA0, bA0, WA1, bA1, WA2, bA2, wA);
    pwl_apply<<<NN, 256>>>(x, A, Wm0, bm0, Wm1, bm1, wf, out);
}